// round 1
// baseline (speedup 1.0000x reference)
#include <cuda_runtime.h>

#define NN 30000
#define DMAXX 16

// ---------------- scratch (static device allocations; no cudaMalloc) -------
__device__ __align__(16) float d_G1[(size_t)NN * 512];    // feat @ Wih1^T + biases
__device__ __align__(16) float d_GB[(size_t)NN * 1024];   // recurrent gate buffer (shared by both layers)
__device__ __align__(16) float d_H1p[(size_t)NN * 128];   // LSTM state, permuted order
__device__ __align__(16) float d_C1p[(size_t)NN * 128];
__device__ __align__(16) float d_M1[(size_t)NN * 128];    // aggregated neighbor hidden, natural order
__device__ __align__(16) float d_X1[(size_t)NN * 256];    // layer-1 output (post relu)
__device__ __align__(16) float d_G2[(size_t)NN * 1024];   // X1 @ Wih2^T + biases
__device__ __align__(16) float d_H2p[(size_t)NN * 256];
__device__ __align__(16) float d_C2p[(size_t)NN * 256];
__device__ __align__(16) float d_M2[(size_t)NN * 256];
__device__ int d_perm[NN];
__device__ int d_hist[17];
__device__ int d_suffix[18];   // d_suffix[t+1] = #nodes with deg > t  (row bound for step t)
__device__ int d_offset[17];

// ---------------- degree counting sort (descending) -------------------------
__global__ void k_hist_zero() {
    int i = threadIdx.x;
    if (i < 17) d_hist[i] = 0;
}
__global__ void k_hist(const int* __restrict__ deg) {
    int n = blockIdx.x * blockDim.x + threadIdx.x;
    if (n < NN) atomicAdd(&d_hist[deg[n]], 1);
}
__global__ void k_scan() {
    // single thread
    d_suffix[17] = 0;
    for (int dd = 16; dd >= 1; --dd) d_suffix[dd] = d_suffix[dd + 1] + d_hist[dd];
    d_suffix[0] = d_suffix[1];
    for (int dd = 1; dd <= 16; ++dd) d_offset[dd] = d_suffix[dd + 1];
}
__global__ void k_scatter(const int* __restrict__ deg) {
    int n = blockIdx.x * blockDim.x + threadIdx.x;
    if (n < NN) {
        int pos = atomicAdd(&d_offset[deg[n]], 1);
        d_perm[pos] = n;
    }
}

// ---------------- zero-init of LSTM states ---------------------------------
__global__ void k_zero_l1() {
    int i = blockIdx.x * blockDim.x + threadIdx.x;
    if (i < NN * 32) {
        ((float4*)d_H1p)[i] = make_float4(0.f, 0.f, 0.f, 0.f);
        ((float4*)d_C1p)[i] = make_float4(0.f, 0.f, 0.f, 0.f);
    }
}
__global__ void k_zero_l2() {
    int i = blockIdx.x * blockDim.x + threadIdx.x;
    if (i < NN * 64) {
        ((float4*)d_H2p)[i] = make_float4(0.f, 0.f, 0.f, 0.f);
        ((float4*)d_C2p)[i] = make_float4(0.f, 0.f, 0.f, 0.f);
    }
}

// ---------------- SGEMM: C[M,Nn] = A[M,K] @ W[Nn,K]^T (+bias) (+=) (relu) ---
template<int BM, int BN, int BK, int TM, int TN, bool ACC, bool RELU>
__global__ void sgemm_nt(const float* __restrict__ A, const float* __restrict__ W,
                         const float* __restrict__ bias0, const float* __restrict__ bias1,
                         float* __restrict__ C, int M, int Nn, int K,
                         const int* rowsDev) {
    constexpr int NT = (BM / TM) * (BN / TN);
    int rows = rowsDev ? *rowsDev : M;
    int rowBase = blockIdx.y * BM;
    if (rowBase >= rows) return;
    int colBase = blockIdx.x * BN;

    __shared__ float As[BK][BM];
    __shared__ float Bs[BK][BN];

    int tid = threadIdx.x;
    int tx = tid % (BN / TN);
    int ty = tid / (BN / TN);

    float acc[TM][TN];
#pragma unroll
    for (int i = 0; i < TM; i++)
#pragma unroll
        for (int j = 0; j < TN; j++) acc[i][j] = 0.f;

    for (int k0 = 0; k0 < K; k0 += BK) {
#pragma unroll 4
        for (int idx = tid; idx < BM * BK; idx += NT) {
            int r = idx / BK, c = idx % BK;
            int gr = rowBase + r;
            As[c][r] = (gr < rows) ? A[(size_t)gr * K + k0 + c] : 0.f;
        }
#pragma unroll 4
        for (int idx = tid; idx < BN * BK; idx += NT) {
            int n = idx / BK, c = idx % BK;
            Bs[c][n] = W[(size_t)(colBase + n) * K + k0 + c];
        }
        __syncthreads();
#pragma unroll
        for (int k = 0; k < BK; k++) {
            float a[TM], b[TN];
#pragma unroll
            for (int i = 0; i < TM; i++) a[i] = As[k][ty * TM + i];
#pragma unroll
            for (int j = 0; j < TN; j++) b[j] = Bs[k][tx * TN + j];
#pragma unroll
            for (int i = 0; i < TM; i++)
#pragma unroll
                for (int j = 0; j < TN; j++) acc[i][j] += a[i] * b[j];
        }
        __syncthreads();
    }

#pragma unroll
    for (int i = 0; i < TM; i++) {
        int gr = rowBase + ty * TM + i;
        if (gr >= rows) continue;
#pragma unroll
        for (int j = 0; j < TN; j++) {
            int gc = colBase + tx * TN + j;
            float v = acc[i][j];
            if (bias0) v += bias0[gc];
            if (bias1) v += bias1[gc];
            if (ACC) v += C[(size_t)gr * Nn + gc];
            if (RELU) v = fmaxf(v, 0.f);
            C[(size_t)gr * Nn + gc] = v;
        }
    }
}

// ---------------- LSTM pointwise steps --------------------------------------
__device__ __forceinline__ float sigm_(float x) { return 1.f / (1.f + __expf(-x)); }

// layer 1: H=128; 32 threads/node, each thread does 4 hidden units
__global__ void lstm_step1(const int* __restrict__ nbr, int t) {
    int cnt = d_suffix[t + 1];
    int idx = blockIdx.x * blockDim.x + threadIdx.x;
    int p = idx >> 5;
    if (p >= cnt) return;
    int lane = idx & 31;
    int node = d_perm[p];
    int nr = nbr[node * DMAXX + t];
    const float4* gb = (const float4*)&d_GB[(size_t)p * 512];
    const float4* gx = (const float4*)&d_G1[(size_t)nr * 512];
    float4 gi = gb[lane],       xi = gx[lane];
    float4 gf = gb[32 + lane],  xf = gx[32 + lane];
    float4 gg = gb[64 + lane],  xg = gx[64 + lane];
    float4 go = gb[96 + lane],  xo = gx[96 + lane];
    float4* cp = (float4*)&d_C1p[(size_t)p * 128];
    float4* hp = (float4*)&d_H1p[(size_t)p * 128];
    float4 c = cp[lane];
    float4 h;
    c.x = sigm_(gf.x + xf.x) * c.x + sigm_(gi.x + xi.x) * tanhf(gg.x + xg.x); h.x = sigm_(go.x + xo.x) * tanhf(c.x);
    c.y = sigm_(gf.y + xf.y) * c.y + sigm_(gi.y + xi.y) * tanhf(gg.y + xg.y); h.y = sigm_(go.y + xo.y) * tanhf(c.y);
    c.z = sigm_(gf.z + xf.z) * c.z + sigm_(gi.z + xi.z) * tanhf(gg.z + xg.z); h.z = sigm_(go.z + xo.z) * tanhf(c.z);
    c.w = sigm_(gf.w + xf.w) * c.w + sigm_(gi.w + xi.w) * tanhf(gg.w + xg.w); h.w = sigm_(go.w + xo.w) * tanhf(c.w);
    cp[lane] = c; hp[lane] = h;
}

// layer 2: H=256; 64 threads/node
__global__ void lstm_step2(const int* __restrict__ nbr, int t) {
    int cnt = d_suffix[t + 1];
    int idx = blockIdx.x * blockDim.x + threadIdx.x;
    int p = idx >> 6;
    if (p >= cnt) return;
    int lane = idx & 63;
    int node = d_perm[p];
    int nr = nbr[node * DMAXX + t];
    const float4* gb = (const float4*)&d_GB[(size_t)p * 1024];
    const float4* gx = (const float4*)&d_G2[(size_t)nr * 1024];
    float4 gi = gb[lane],        xi = gx[lane];
    float4 gf = gb[64 + lane],   xf = gx[64 + lane];
    float4 gg = gb[128 + lane],  xg = gx[128 + lane];
    float4 go = gb[192 + lane],  xo = gx[192 + lane];
    float4* cp = (float4*)&d_C2p[(size_t)p * 256];
    float4* hp = (float4*)&d_H2p[(size_t)p * 256];
    float4 c = cp[lane];
    float4 h;
    c.x = sigm_(gf.x + xf.x) * c.x + sigm_(gi.x + xi.x) * tanhf(gg.x + xg.x); h.x = sigm_(go.x + xo.x) * tanhf(c.x);
    c.y = sigm_(gf.y + xf.y) * c.y + sigm_(gi.y + xi.y) * tanhf(gg.y + xg.y); h.y = sigm_(go.y + xo.y) * tanhf(c.y);
    c.z = sigm_(gf.z + xf.z) * c.z + sigm_(gi.z + xi.z) * tanhf(gg.z + xg.z); h.z = sigm_(go.z + xo.z) * tanhf(c.z);
    c.w = sigm_(gf.w + xf.w) * c.w + sigm_(gi.w + xi.w) * tanhf(gg.w + xg.w); h.w = sigm_(go.w + xo.w) * tanhf(c.w);
    cp[lane] = c; hp[lane] = h;
}

// scatter permuted final hidden state back to natural node order
__global__ void k_scatter_h1() {
    int idx = blockIdx.x * blockDim.x + threadIdx.x;
    if (idx >= NN * 32) return;
    int p = idx >> 5, lane = idx & 31;
    int node = d_perm[p];
    ((float4*)d_M1)[node * 32 + lane] = ((const float4*)d_H1p)[p * 32 + lane];
}
__global__ void k_scatter_h2() {
    int idx = blockIdx.x * blockDim.x + threadIdx.x;
    if (idx >= NN * 64) return;
    int p = idx >> 6, lane = idx & 63;
    int node = d_perm[p];
    ((float4*)d_M2)[node * 64 + lane] = ((const float4*)d_H2p)[p * 64 + lane];
}

// ---------------- launch -----------------------------------------------------
extern "C" void kernel_launch(void* const* d_in, const int* in_sizes, int n_in,
                              void* d_out, int out_size) {
    const float* feat    = (const float*)d_in[0];
    const int*   nbr     = (const int*)  d_in[1];
    const int*   deg     = (const int*)  d_in[2];
    const float* Wih1    = (const float*)d_in[3];
    const float* Whh1    = (const float*)d_in[4];
    const float* bih1    = (const float*)d_in[5];
    const float* bhh1    = (const float*)d_in[6];
    const float* Wself1  = (const float*)d_in[7];
    const float* Wneigh1 = (const float*)d_in[8];
    const float* b1      = (const float*)d_in[9];
    const float* Wih2    = (const float*)d_in[10];
    const float* Whh2    = (const float*)d_in[11];
    const float* bih2    = (const float*)d_in[12];
    const float* bhh2    = (const float*)d_in[13];
    const float* Wself2  = (const float*)d_in[14];
    const float* Wneigh2 = (const float*)d_in[15];
    const float* b2      = (const float*)d_in[16];
    float* out = (float*)d_out;

    float *pG1, *pGB, *pH1, *pM1, *pX1, *pG2, *pH2, *pM2;
    int* pSuf;
    cudaGetSymbolAddress((void**)&pG1, d_G1);
    cudaGetSymbolAddress((void**)&pGB, d_GB);
    cudaGetSymbolAddress((void**)&pH1, d_H1p);
    cudaGetSymbolAddress((void**)&pM1, d_M1);
    cudaGetSymbolAddress((void**)&pX1, d_X1);
    cudaGetSymbolAddress((void**)&pG2, d_G2);
    cudaGetSymbolAddress((void**)&pH2, d_H2p);
    cudaGetSymbolAddress((void**)&pM2, d_M2);
    cudaGetSymbolAddress((void**)&pSuf, d_suffix);

    const int MB = (NN + 127) / 128;  // 235 row blocks

    // degree sort (descending buckets): perm + suffix counts
    k_hist_zero<<<1, 32>>>();
    k_hist<<<(NN + 255) / 256, 256>>>(deg);
    k_scan<<<1, 1>>>();
    k_scatter<<<(NN + 255) / 256, 256>>>(deg);

    // ---------------- layer 1 ----------------
    // G1 = feat @ Wih1^T + bih1 + bhh1
    sgemm_nt<128, 128, 16, 8, 8, false, false><<<dim3(4, MB), 256>>>(
        feat, Wih1, bih1, bhh1, pG1, NN, 512, 128, nullptr);
    k_zero_l1<<<(NN * 32 + 255) / 256, 256>>>();
    for (int t = 0; t < DMAXX; t++) {
        sgemm_nt<128, 128, 16, 8, 8, false, false><<<dim3(4, MB), 256>>>(
            pH1, Whh1, nullptr, nullptr, pGB, NN, 512, 128, pSuf + (t + 1));
        lstm_step1<<<(NN * 32 + 255) / 256, 256>>>(nbr, t);
    }
    k_scatter_h1<<<(NN * 32 + 255) / 256, 256>>>();
    // X1 = relu(feat@Wself1^T + M1@Wneigh1^T + b1)
    sgemm_nt<128, 128, 16, 8, 8, false, false><<<dim3(2, MB), 256>>>(
        feat, Wself1, b1, nullptr, pX1, NN, 256, 128, nullptr);
    sgemm_nt<128, 128, 16, 8, 8, true, true><<<dim3(2, MB), 256>>>(
        pM1, Wneigh1, nullptr, nullptr, pX1, NN, 256, 128, nullptr);

    // ---------------- layer 2 ----------------
    sgemm_nt<128, 128, 16, 8, 8, false, false><<<dim3(8, MB), 256>>>(
        pX1, Wih2, bih2, bhh2, pG2, NN, 1024, 256, nullptr);
    k_zero_l2<<<(NN * 64 + 255) / 256, 256>>>();
    for (int t = 0; t < DMAXX; t++) {
        sgemm_nt<128, 128, 16, 8, 8, false, false><<<dim3(8, MB), 256>>>(
            pH2, Whh2, nullptr, nullptr, pGB, NN, 1024, 256, pSuf + (t + 1));
        lstm_step2<<<(NN * 64 + 255) / 256, 256>>>(nbr, t);
    }
    k_scatter_h2<<<(NN * 64 + 255) / 256, 256>>>();
    // out = X1@Wself2^T + M2@Wneigh2^T + b2
    sgemm_nt<128, 64, 16, 8, 4, false, false><<<dim3(1, MB), 256>>>(
        pX1, Wself2, b2, nullptr, out, NN, 64, 256, nullptr);
    sgemm_nt<128, 64, 16, 8, 4, true, false><<<dim3(1, MB), 256>>>(
        pM2, Wneigh2, nullptr, nullptr, out, NN, 64, 256, nullptr);
}

// round 2
// speedup vs baseline: 3.3603x; 3.3603x over previous
#include <cuda_runtime.h>
#include <cstdint>

#define NN 30000
#define DMAXX 16

// ---------------- scratch (static device allocations; no cudaMalloc) -------
__device__ __align__(16) float d_G1[(size_t)NN * 512];    // feat @ Wih1^T + biases
__device__ __align__(16) float d_GB[(size_t)NN * 1024];   // recurrent gate buffer (shared by both layers)
__device__ __align__(16) float d_H1p[(size_t)NN * 128];   // LSTM state, permuted order
__device__ __align__(16) float d_C1p[(size_t)NN * 128];
__device__ __align__(16) float d_M1[(size_t)NN * 128];    // aggregated neighbor hidden, natural order
__device__ __align__(16) float d_X1[(size_t)NN * 256];    // layer-1 output (post relu)
__device__ __align__(16) float d_G2[(size_t)NN * 1024];   // X1 @ Wih2^T + biases
__device__ __align__(16) float d_H2p[(size_t)NN * 256];
__device__ __align__(16) float d_C2p[(size_t)NN * 256];
__device__ __align__(16) float d_M2[(size_t)NN * 256];
__device__ int d_perm[NN];
__device__ int d_hist[17];
__device__ int d_suffix[18];   // d_suffix[t+1] = #nodes with deg > t  (row bound for step t)
__device__ int d_offset[17];

// ---------------- degree counting sort (descending) -------------------------
__global__ void k_hist_zero() {
    int i = threadIdx.x;
    if (i < 17) d_hist[i] = 0;
}
__global__ void k_hist(const int* __restrict__ deg) {
    int n = blockIdx.x * blockDim.x + threadIdx.x;
    if (n < NN) atomicAdd(&d_hist[deg[n]], 1);
}
__global__ void k_scan() {
    d_suffix[17] = 0;
    for (int dd = 16; dd >= 1; --dd) d_suffix[dd] = d_suffix[dd + 1] + d_hist[dd];
    d_suffix[0] = d_suffix[1];
    for (int dd = 1; dd <= 16; ++dd) d_offset[dd] = d_suffix[dd + 1];
}
__global__ void k_scatter(const int* __restrict__ deg) {
    int n = blockIdx.x * blockDim.x + threadIdx.x;
    if (n < NN) {
        int pos = atomicAdd(&d_offset[deg[n]], 1);
        d_perm[pos] = n;
    }
}

// ---------------- zero-init of LSTM states ---------------------------------
__global__ void k_zero_l1() {
    int i = blockIdx.x * blockDim.x + threadIdx.x;
    if (i < NN * 32) {
        ((float4*)d_H1p)[i] = make_float4(0.f, 0.f, 0.f, 0.f);
        ((float4*)d_C1p)[i] = make_float4(0.f, 0.f, 0.f, 0.f);
    }
}
__global__ void k_zero_l2() {
    int i = blockIdx.x * blockDim.x + threadIdx.x;
    if (i < NN * 64) {
        ((float4*)d_H2p)[i] = make_float4(0.f, 0.f, 0.f, 0.f);
        ((float4*)d_C2p)[i] = make_float4(0.f, 0.f, 0.f, 0.f);
    }
}

// ---------------- tf32 helpers ----------------------------------------------
__device__ __forceinline__ uint32_t f2tf32(float x) {
    uint32_t y;
    asm("cvt.rna.tf32.f32 %0, %1;" : "=r"(y) : "f"(x));
    return y;
}

__device__ __forceinline__ void mma_tf32(float& c0, float& c1, float& c2, float& c3,
                                         uint32_t a0, uint32_t a1, uint32_t a2, uint32_t a3,
                                         uint32_t b0, uint32_t b1) {
    asm volatile(
        "mma.sync.aligned.m16n8k8.row.col.f32.tf32.tf32.f32 "
        "{%0,%1,%2,%3}, {%4,%5,%6,%7}, {%8,%9}, {%0,%1,%2,%3};"
        : "+f"(c0), "+f"(c1), "+f"(c2), "+f"(c3)
        : "r"(a0), "r"(a1), "r"(a2), "r"(a3), "r"(b0), "r"(b1));
}

// ---------------- tf32 tensor-core GEMM: C[M,Nn] = A[M,K] @ W[Nn,K]^T --------
// BK = 16. 8 warps / 256 threads. Warp tile WM x WN via m16n8k8 micro tiles.
template<int BM, int BN, int WARPS_M, int WARPS_N, bool ACC, bool RELU>
__global__ __launch_bounds__(256)
void tgemm_nt(const float* __restrict__ A, const float* __restrict__ W,
              const float* __restrict__ bias0, const float* __restrict__ bias1,
              float* __restrict__ C, int M, int Nn, int K,
              const int* rowsDev) {
    constexpr int BK = 16;
    constexpr int LDS_ = BK + 4;           // padded stride (floats) -> conflict-free
    constexpr int WM = BM / WARPS_M;
    constexpr int WN = BN / WARPS_N;
    constexpr int MT = WM / 16;
    constexpr int NTT = WN / 8;
    constexpr int NTHR = WARPS_M * WARPS_N * 32;

    int rows = rowsDev ? *rowsDev : M;
    int rowBase = blockIdx.y * BM;
    if (rowBase >= rows) return;
    int colBase = blockIdx.x * BN;

    __shared__ uint32_t As[BM * LDS_];
    __shared__ uint32_t Bs[BN * LDS_];

    int tid = threadIdx.x;
    int wid = tid >> 5;
    int lane = tid & 31;
    int wm = wid / WARPS_N;                // warp row
    int wn = wid % WARPS_N;                // warp col
    int grp = lane >> 2;                   // 0..7
    int tg = lane & 3;                     // 0..3

    float acc[MT][NTT][4];
#pragma unroll
    for (int i = 0; i < MT; i++)
#pragma unroll
        for (int j = 0; j < NTT; j++) {
            acc[i][j][0] = 0.f; acc[i][j][1] = 0.f; acc[i][j][2] = 0.f; acc[i][j][3] = 0.f;
        }

    for (int k0 = 0; k0 < K; k0 += BK) {
        // load A tile (guard rows), convert to tf32
#pragma unroll 2
        for (int idx = tid; idx < BM * 4; idx += NTHR) {
            int r = idx >> 2, c4 = (idx & 3) << 2;
            int gr = rowBase + r;
            float4 v = make_float4(0.f, 0.f, 0.f, 0.f);
            if (gr < rows) v = *(const float4*)&A[(size_t)gr * K + k0 + c4];
            uint32_t* dst = &As[r * LDS_ + c4];
            dst[0] = f2tf32(v.x); dst[1] = f2tf32(v.y); dst[2] = f2tf32(v.z); dst[3] = f2tf32(v.w);
        }
        // load W tile
#pragma unroll 2
        for (int idx = tid; idx < BN * 4; idx += NTHR) {
            int r = idx >> 2, c4 = (idx & 3) << 2;
            float4 v = *(const float4*)&W[(size_t)(colBase + r) * K + k0 + c4];
            uint32_t* dst = &Bs[r * LDS_ + c4];
            dst[0] = f2tf32(v.x); dst[1] = f2tf32(v.y); dst[2] = f2tf32(v.z); dst[3] = f2tf32(v.w);
        }
        __syncthreads();

#pragma unroll
        for (int kk = 0; kk < BK; kk += 8) {
            uint32_t af[MT][4];
#pragma unroll
            for (int i = 0; i < MT; i++) {
                int r0 = wm * WM + i * 16 + grp;
                int c = kk + tg;
                af[i][0] = As[r0 * LDS_ + c];
                af[i][1] = As[(r0 + 8) * LDS_ + c];
                af[i][2] = As[r0 * LDS_ + c + 4];
                af[i][3] = As[(r0 + 8) * LDS_ + c + 4];
            }
            uint32_t bf[NTT][2];
#pragma unroll
            for (int j = 0; j < NTT; j++) {
                int n0 = wn * WN + j * 8 + grp;
                bf[j][0] = Bs[n0 * LDS_ + kk + tg];
                bf[j][1] = Bs[n0 * LDS_ + kk + tg + 4];
            }
#pragma unroll
            for (int i = 0; i < MT; i++)
#pragma unroll
                for (int j = 0; j < NTT; j++)
                    mma_tf32(acc[i][j][0], acc[i][j][1], acc[i][j][2], acc[i][j][3],
                             af[i][0], af[i][1], af[i][2], af[i][3], bf[j][0], bf[j][1]);
        }
        __syncthreads();
    }

    // epilogue: c0,c1 at (row, 2*tg), c2,c3 at (row+8, 2*tg)
#pragma unroll
    for (int i = 0; i < MT; i++) {
#pragma unroll
        for (int j = 0; j < NTT; j++) {
            int gc = colBase + wn * WN + j * 8 + 2 * tg;
            int gr0 = rowBase + wm * WM + i * 16 + grp;
            float b = 0.f;
            if (bias0) b += bias0[gc];
            if (bias1) b += bias1[gc];
            float b_1 = 0.f;
            if (bias0) b_1 += bias0[gc + 1];
            if (bias1) b_1 += bias1[gc + 1];
            if (gr0 < rows) {
                float v0 = acc[i][j][0] + b, v1 = acc[i][j][1] + b_1;
                float* p = &C[(size_t)gr0 * Nn + gc];
                if (ACC) { v0 += p[0]; v1 += p[1]; }
                if (RELU) { v0 = fmaxf(v0, 0.f); v1 = fmaxf(v1, 0.f); }
                *(float2*)p = make_float2(v0, v1);
            }
            int gr1 = gr0 + 8;
            if (gr1 < rows) {
                float v0 = acc[i][j][2] + b, v1 = acc[i][j][3] + b_1;
                float* p = &C[(size_t)gr1 * Nn + gc];
                if (ACC) { v0 += p[0]; v1 += p[1]; }
                if (RELU) { v0 = fmaxf(v0, 0.f); v1 = fmaxf(v1, 0.f); }
                *(float2*)p = make_float2(v0, v1);
            }
        }
    }
}

// ---------------- LSTM pointwise steps --------------------------------------
__device__ __forceinline__ float sigm_(float x) { return 1.f / (1.f + __expf(-x)); }

// layer 1: H=128; 32 threads/node, each thread does 4 hidden units
__global__ void lstm_step1(const int* __restrict__ nbr, int t) {
    int cnt = d_suffix[t + 1];
    int idx = blockIdx.x * blockDim.x + threadIdx.x;
    int p = idx >> 5;
    if (p >= cnt) return;
    int lane = idx & 31;
    int node = d_perm[p];
    int nr = nbr[node * DMAXX + t];
    const float4* gb = (const float4*)&d_GB[(size_t)p * 512];
    const float4* gx = (const float4*)&d_G1[(size_t)nr * 512];
    float4 gi = gb[lane],       xi = gx[lane];
    float4 gf = gb[32 + lane],  xf = gx[32 + lane];
    float4 gg = gb[64 + lane],  xg = gx[64 + lane];
    float4 go = gb[96 + lane],  xo = gx[96 + lane];
    float4* cp = (float4*)&d_C1p[(size_t)p * 128];
    float4* hp = (float4*)&d_H1p[(size_t)p * 128];
    float4 c = cp[lane];
    float4 h;
    c.x = sigm_(gf.x + xf.x) * c.x + sigm_(gi.x + xi.x) * tanhf(gg.x + xg.x); h.x = sigm_(go.x + xo.x) * tanhf(c.x);
    c.y = sigm_(gf.y + xf.y) * c.y + sigm_(gi.y + xi.y) * tanhf(gg.y + xg.y); h.y = sigm_(go.y + xo.y) * tanhf(c.y);
    c.z = sigm_(gf.z + xf.z) * c.z + sigm_(gi.z + xi.z) * tanhf(gg.z + xg.z); h.z = sigm_(go.z + xo.z) * tanhf(c.z);
    c.w = sigm_(gf.w + xf.w) * c.w + sigm_(gi.w + xi.w) * tanhf(gg.w + xg.w); h.w = sigm_(go.w + xo.w) * tanhf(c.w);
    cp[lane] = c; hp[lane] = h;
}

// layer 2: H=256; 64 threads/node
__global__ void lstm_step2(const int* __restrict__ nbr, int t) {
    int cnt = d_suffix[t + 1];
    int idx = blockIdx.x * blockDim.x + threadIdx.x;
    int p = idx >> 6;
    if (p >= cnt) return;
    int lane = idx & 63;
    int node = d_perm[p];
    int nr = nbr[node * DMAXX + t];
    const float4* gb = (const float4*)&d_GB[(size_t)p * 1024];
    const float4* gx = (const float4*)&d_G2[(size_t)nr * 1024];
    float4 gi = gb[lane],        xi = gx[lane];
    float4 gf = gb[64 + lane],   xf = gx[64 + lane];
    float4 gg = gb[128 + lane],  xg = gx[128 + lane];
    float4 go = gb[192 + lane],  xo = gx[192 + lane];
    float4* cp = (float4*)&d_C2p[(size_t)p * 256];
    float4* hp = (float4*)&d_H2p[(size_t)p * 256];
    float4 c = cp[lane];
    float4 h;
    c.x = sigm_(gf.x + xf.x) * c.x + sigm_(gi.x + xi.x) * tanhf(gg.x + xg.x); h.x = sigm_(go.x + xo.x) * tanhf(c.x);
    c.y = sigm_(gf.y + xf.y) * c.y + sigm_(gi.y + xi.y) * tanhf(gg.y + xg.y); h.y = sigm_(go.y + xo.y) * tanhf(c.y);
    c.z = sigm_(gf.z + xf.z) * c.z + sigm_(gi.z + xi.z) * tanhf(gg.z + xg.z); h.z = sigm_(go.z + xo.z) * tanhf(c.z);
    c.w = sigm_(gf.w + xf.w) * c.w + sigm_(gi.w + xi.w) * tanhf(gg.w + xg.w); h.w = sigm_(go.w + xo.w) * tanhf(c.w);
    cp[lane] = c; hp[lane] = h;
}

// scatter permuted final hidden state back to natural node order
__global__ void k_scatter_h1() {
    int idx = blockIdx.x * blockDim.x + threadIdx.x;
    if (idx >= NN * 32) return;
    int p = idx >> 5, lane = idx & 31;
    int node = d_perm[p];
    ((float4*)d_M1)[node * 32 + lane] = ((const float4*)d_H1p)[p * 32 + lane];
}
__global__ void k_scatter_h2() {
    int idx = blockIdx.x * blockDim.x + threadIdx.x;
    if (idx >= NN * 64) return;
    int p = idx >> 6, lane = idx & 63;
    int node = d_perm[p];
    ((float4*)d_M2)[node * 64 + lane] = ((const float4*)d_H2p)[p * 64 + lane];
}

// ---------------- launch -----------------------------------------------------
extern "C" void kernel_launch(void* const* d_in, const int* in_sizes, int n_in,
                              void* d_out, int out_size) {
    const float* feat    = (const float*)d_in[0];
    const int*   nbr     = (const int*)  d_in[1];
    const int*   deg     = (const int*)  d_in[2];
    const float* Wih1    = (const float*)d_in[3];
    const float* Whh1    = (const float*)d_in[4];
    const float* bih1    = (const float*)d_in[5];
    const float* bhh1    = (const float*)d_in[6];
    const float* Wself1  = (const float*)d_in[7];
    const float* Wneigh1 = (const float*)d_in[8];
    const float* b1      = (const float*)d_in[9];
    const float* Wih2    = (const float*)d_in[10];
    const float* Whh2    = (const float*)d_in[11];
    const float* bih2    = (const float*)d_in[12];
    const float* bhh2    = (const float*)d_in[13];
    const float* Wself2  = (const float*)d_in[14];
    const float* Wneigh2 = (const float*)d_in[15];
    const float* b2      = (const float*)d_in[16];
    float* out = (float*)d_out;

    float *pG1, *pGB, *pH1, *pM1, *pX1, *pG2, *pH2, *pM2;
    int* pSuf;
    cudaGetSymbolAddress((void**)&pG1, d_G1);
    cudaGetSymbolAddress((void**)&pGB, d_GB);
    cudaGetSymbolAddress((void**)&pH1, d_H1p);
    cudaGetSymbolAddress((void**)&pM1, d_M1);
    cudaGetSymbolAddress((void**)&pX1, d_X1);
    cudaGetSymbolAddress((void**)&pG2, d_G2);
    cudaGetSymbolAddress((void**)&pH2, d_H2p);
    cudaGetSymbolAddress((void**)&pM2, d_M2);
    cudaGetSymbolAddress((void**)&pSuf, d_suffix);

    const int MB = (NN + 127) / 128;  // 235 row blocks

    // degree sort (descending buckets): perm + suffix counts
    k_hist_zero<<<1, 32>>>();
    k_hist<<<(NN + 255) / 256, 256>>>(deg);
    k_scan<<<1, 1>>>();
    k_scatter<<<(NN + 255) / 256, 256>>>(deg);

    // ---------------- layer 1 ----------------
    // G1 = feat @ Wih1^T + bih1 + bhh1
    tgemm_nt<128, 128, 2, 4, false, false><<<dim3(4, MB), 256>>>(
        feat, Wih1, bih1, bhh1, pG1, NN, 512, 128, nullptr);
    k_zero_l1<<<(NN * 32 + 255) / 256, 256>>>();
    for (int t = 0; t < DMAXX; t++) {
        tgemm_nt<128, 128, 2, 4, false, false><<<dim3(4, MB), 256>>>(
            pH1, Whh1, nullptr, nullptr, pGB, NN, 512, 128, pSuf + (t + 1));
        lstm_step1<<<(NN * 32 + 255) / 256, 256>>>(nbr, t);
    }
    k_scatter_h1<<<(NN * 32 + 255) / 256, 256>>>();
    // X1 = relu(feat@Wself1^T + M1@Wneigh1^T + b1)
    tgemm_nt<128, 128, 2, 4, false, false><<<dim3(2, MB), 256>>>(
        feat, Wself1, b1, nullptr, pX1, NN, 256, 128, nullptr);
    tgemm_nt<128, 128, 2, 4, true, true><<<dim3(2, MB), 256>>>(
        pM1, Wneigh1, nullptr, nullptr, pX1, NN, 256, 128, nullptr);

    // ---------------- layer 2 ----------------
    tgemm_nt<128, 128, 2, 4, false, false><<<dim3(8, MB), 256>>>(
        pX1, Wih2, bih2, bhh2, pG2, NN, 1024, 256, nullptr);
    k_zero_l2<<<(NN * 64 + 255) / 256, 256>>>();
    for (int t = 0; t < DMAXX; t++) {
        tgemm_nt<128, 128, 2, 4, false, false><<<dim3(8, MB), 256>>>(
            pH2, Whh2, nullptr, nullptr, pGB, NN, 1024, 256, pSuf + (t + 1));
        lstm_step2<<<(NN * 64 + 255) / 256, 256>>>(nbr, t);
    }
    k_scatter_h2<<<(NN * 64 + 255) / 256, 256>>>();
    // out = X1@Wself2^T + M2@Wneigh2^T + b2
    tgemm_nt<128, 64, 4, 2, false, false><<<dim3(1, MB), 256>>>(
        pX1, Wself2, b2, nullptr, out, NN, 64, 256, nullptr);
    tgemm_nt<128, 64, 4, 2, true, false><<<dim3(1, MB), 256>>>(
        pM2, Wneigh2, nullptr, nullptr, out, NN, 64, 256, nullptr);
}